// round 5
// baseline (speedup 1.0000x reference)
#include <cuda_runtime.h>
#include <cuda_bf16.h>

#define SS 4096
#define KK 64
#define NN 4096
#define GG 512
#define PP (SS*KK)

// ---------------- scratch (no allocation allowed) ----------------
__device__ int d_flag64;
__device__ __align__(16) int d_mi[PP];
__device__ __align__(16) int d_ai[PP];
__device__ __align__(16) int d_phi[PP];
__device__ __align__(16) int d_cnt[SS];
__device__ __align__(16) __nv_bfloat16 d_gb[NN*GG];        // g_i in bf16
__device__ __align__(16) __nv_bfloat16 d_wct[160*512];     // W1c^T [n=160][k=512] bf16, zero-padded n>=150
__device__ __align__(16) float d_U[NN*160];                // g @ W1a, pad cols zero
__device__ __align__(16) float d_V[NN*160];                // g @ W1b
__device__ __align__(16) float d_T[192*160];               // phi-combo @ W1d + b1

// ---------------- helpers ----------------
__device__ __forceinline__ unsigned bmul2(unsigned x, unsigned y) {
    __nv_bfloat162 a = *reinterpret_cast<__nv_bfloat162*>(&x);
    __nv_bfloat162 b = *reinterpret_cast<__nv_bfloat162*>(&y);
    __nv_bfloat162 r = __hmul2(a, b);
    return *reinterpret_cast<unsigned*>(&r);
}

// ---------------- precompute kernels ----------------
__global__ void k_detect(const unsigned* __restrict__ m) {
    if (threadIdx.x == 0) {
        unsigned acc = 0;
        for (int t = 0; t < 64; t++) acc |= m[2*t + 1];
        d_flag64 = (acc == 0) ? 1 : 0;   // all odd words zero -> data is int64
    }
}

__global__ void k_index(const void* __restrict__ mi, const void* __restrict__ ai,
                        const void* __restrict__ di, const void* __restrict__ ge,
                        const void* __restrict__ sp, const void* __restrict__ ac) {
    int p = blockIdx.x * blockDim.x + threadIdx.x;
    int f = d_flag64;
    if (p < PP) {
        int a, b; long long d, gg, ss;
        if (f) {
            a = (int)((const long long*)mi)[p];
            b = (int)((const long long*)ai)[p];
            d  = ((const long long*)di)[p];
            gg = ((const long long*)ge)[p];
            ss = ((const long long*)sp)[p];
        } else {
            a = ((const int*)mi)[p];
            b = ((const int*)ai)[p];
            d  = ((const int*)di)[p];
            gg = ((const int*)ge)[p];
            ss = ((const int*)sp)[p];
        }
        int bk = (d>=1)+(d>=2)+(d>=3)+(d>=4)+(d>=8)+(d>=16)+(d>=32)+(d>=64);
        d_mi[p] = a;
        d_ai[p] = b;
        d_phi[p] = bk*21 + (int)gg*3 + (int)ss;
    }
    if (p < SS) {
        d_cnt[p] = f ? (int)((const long long*)ac)[p] : ((const int*)ac)[p];
    }
}

__global__ void k_gb(const float* __restrict__ g) {
    int i = blockIdx.x * 256 + threadIdx.x;
    if (i < NN*GG) d_gb[i] = __float2bfloat16(g[i]);
}

__global__ void k_wct(const float* __restrict__ W1) {
    int i = blockIdx.x * 256 + threadIdx.x;
    if (i < 160*512) {
        int n = i >> 9, k = i & 511;
        float v = (n < 150) ? W1[(size_t)(1024 + k)*150 + n] : 0.f;
        d_wct[i] = __float2bfloat16(v);
    }
}

__global__ void k_T(const float* __restrict__ de, const float* __restrict__ ge,
                    const float* __restrict__ se, const float* __restrict__ W1,
                    const float* __restrict__ b1) {
    int gid = blockIdx.x * blockDim.x + threadIdx.x;
    if (gid >= 192*160) return;
    int c = gid / 160, m = gid % 160;
    int d = c / 21, rr = c % 21, gg = rr / 3, sp = rr % 3;
    float val = 0.f;
    if (m < 150 && d < 9) {
        val = b1[m];
        #pragma unroll 4
        for (int q = 0; q < 20; q++) {
            val += de[d*20 + q]  * W1[(size_t)(1536 + q)*150 + m];
            val += ge[gg*20 + q] * W1[(size_t)(1556 + q)*150 + m];
            val += se[sp*20 + q] * W1[(size_t)(1576 + q)*150 + m];
        }
    }
    d_T[gid] = val;
}

// U[n][m] = sum_k g[n][k] W1[k][m]      (k = 0..511)
// V[n][m] = sum_k g[n][k] W1[512+k][m]
__global__ __launch_bounds__(160) void k_uv(const float* __restrict__ g,
                                            const float* __restrict__ W1) {
    __shared__ float gs[8*512];
    int n0 = blockIdx.x * 8;
    for (int idx = threadIdx.x; idx < 8*512; idx += 160)
        gs[idx] = g[(size_t)n0*512 + idx];
    __syncthreads();
    int m = threadIdx.x;
    if (m < 150) {
        float aU[8], aV[8];
        #pragma unroll
        for (int r = 0; r < 8; r++) { aU[r] = 0.f; aV[r] = 0.f; }
        for (int k = 0; k < 512; k++) {
            float wu = W1[(size_t)k*150 + m];
            float wv = W1[(size_t)(512 + k)*150 + m];
            #pragma unroll
            for (int r = 0; r < 8; r++) {
                float gv = gs[r*512 + k];
                aU[r] = fmaf(gv, wu, aU[r]);
                aV[r] = fmaf(gv, wv, aV[r]);
            }
        }
        #pragma unroll
        for (int r = 0; r < 8; r++) {
            d_U[(size_t)(n0 + r)*160 + m] = aU[r];
            d_V[(size_t)(n0 + r)*160 + m] = aV[r];
        }
    } else {
        #pragma unroll
        for (int r = 0; r < 8; r++) {
            d_U[(size_t)(n0 + r)*160 + m] = 0.f;
            d_V[(size_t)(n0 + r)*160 + m] = 0.f;
        }
    }
}

// ---------------- main fused kernel ----------------
// CTA = 128 pairs = 2 spans. 256 threads, 8 warps (4 M-tiles x 2 N-tiles).
// smem layout (bytes):
//   Es    [128][552] bf16   @ 0        (141312)
//   Hp    [128][160] bf16   @ 141312   ( 40960)   U+V+T (+b1) per pair
//   Wcs   [160][20]  bf16   @ 182272   (  6400)   W1c^T k-chunk, stride 20 => conflict-free
//   W2s   [160]      f32    @ 188672   (   640)
//   msum  [128]      f32    @ 189312
//   scores[128]      f32    @ 189824
//   sred  [128][2]   f32    @ 190336
#define SMEM_MAIN 191360

__global__ __launch_bounds__(256, 1) void k_main(const float* __restrict__ ms,
                                                 const float* __restrict__ W2,
                                                 const float* __restrict__ b2,
                                                 float* __restrict__ out) {
    extern __shared__ char sm[];
    __nv_bfloat16* Es  = (__nv_bfloat16*)(sm);
    __nv_bfloat16* Hp  = (__nv_bfloat16*)(sm + 141312);
    __nv_bfloat16* Wcs = (__nv_bfloat16*)(sm + 182272);
    float* W2s    = (float*)(sm + 188672);
    float* msum   = (float*)(sm + 189312);
    float* scores = (float*)(sm + 189824);
    float* sred   = (float*)(sm + 190336);

    const int t = threadIdx.x;
    const int pbase = blockIdx.x * 128;

    // ---- Phase A: gather + elementwise product + Hpre tile ----
    {
        int pl = t >> 1, half = t & 1;
        int p = pbase + pl;
        int i = d_mi[p], j = d_ai[p], c = d_phi[p];
        if (half == 0) msum[pl] = ms[i] + ms[j];
        const uint4* gi4 = (const uint4*)(d_gb + (size_t)i*GG + half*256);
        const uint4* gj4 = (const uint4*)(d_gb + (size_t)j*GG + half*256);
        uint4* e4 = (uint4*)(Es + pl*552 + half*256);
        #pragma unroll 8
        for (int kkx = 0; kkx < 32; kkx++) {
            uint4 a = gi4[kkx], b = gj4[kkx], r;
            r.x = bmul2(a.x, b.x);
            r.y = bmul2(a.y, b.y);
            r.z = bmul2(a.z, b.z);
            r.w = bmul2(a.w, b.w);
            e4[kkx] = r;
        }
        const float4* u4 = (const float4*)(d_U + (size_t)i*160 + half*80);
        const float4* v4 = (const float4*)(d_V + (size_t)j*160 + half*80);
        const float4* t4v = (const float4*)(d_T + (size_t)c*160 + half*80);
        uint2* h8 = (uint2*)(Hp + pl*160 + half*80);
        #pragma unroll 5
        for (int q = 0; q < 20; q++) {
            float4 a = u4[q], b = v4[q], cc = t4v[q];
            __nv_bfloat162 p0 = __floats2bfloat162_rn(a.x + b.x + cc.x, a.y + b.y + cc.y);
            __nv_bfloat162 p1 = __floats2bfloat162_rn(a.z + b.z + cc.z, a.w + b.w + cc.w);
            uint2 st;
            st.x = *(unsigned*)&p0;
            st.y = *(unsigned*)&p1;
            h8[q] = st;
        }
        if (t < 160) W2s[t] = (t < 150) ? __ldg(W2 + t) : 0.f;
    }

    // ---- Phase B: (i*j) @ W1c via mma.sync bf16 ----
    const int lane = t & 31, warp = t >> 5;
    const int g = lane >> 2, t4 = lane & 3;
    const int rm = (warp & 3) * 32;   // M base (rows)
    const int wn = warp >> 2;
    const int cn = wn * 80;           // N base (cols)

    float acc[2][10][4];
    #pragma unroll
    for (int mf = 0; mf < 2; mf++)
        #pragma unroll
        for (int nf = 0; nf < 10; nf++)
            #pragma unroll
            for (int q = 0; q < 4; q++) acc[mf][nf][q] = 0.f;

    for (int ks = 0; ks < 32; ks++) {
        const int kb = ks * 16;
        __syncthreads();   // previous chunk fully consumed (also covers Phase A)
        // load W1c^T k-chunk: [160 n][16 k] -> smem stride 20
        #pragma unroll
        for (int q = 0; q < 5; q++) {
            int e = t + q * 256;
            int n = e >> 3, k2 = e & 7;
            *(unsigned*)(Wcs + n*20 + k2*2) =
                *(const unsigned*)(d_wct + (size_t)n*512 + kb + k2*2);
        }
        __syncthreads();

        unsigned a[2][4];
        #pragma unroll
        for (int mf = 0; mf < 2; mf++) {
            const __nv_bfloat16* er = Es + (rm + mf*16 + g)*552 + kb + 2*t4;
            a[mf][0] = *(const unsigned*)(er);
            a[mf][1] = *(const unsigned*)(er + 8*552);
            a[mf][2] = *(const unsigned*)(er + 8);
            a[mf][3] = *(const unsigned*)(er + 8*552 + 8);
        }
        #pragma unroll
        for (int nf = 0; nf < 10; nf++) {
            const __nv_bfloat16* br = Wcs + (cn + nf*8 + g)*20 + 2*t4;
            unsigned b0 = *(const unsigned*)(br);
            unsigned b1r = *(const unsigned*)(br + 8);
            #pragma unroll
            for (int mf = 0; mf < 2; mf++) {
                asm volatile(
                    "mma.sync.aligned.m16n8k16.row.col.f32.bf16.bf16.f32 "
                    "{%0,%1,%2,%3}, {%4,%5,%6,%7}, {%8,%9}, {%0,%1,%2,%3};"
                    : "+f"(acc[mf][nf][0]), "+f"(acc[mf][nf][1]),
                      "+f"(acc[mf][nf][2]), "+f"(acc[mf][nf][3])
                    : "r"(a[mf][0]), "r"(a[mf][1]), "r"(a[mf][2]), "r"(a[mf][3]),
                      "r"(b0), "r"(b1r));
            }
        }
    }

    // ---- Phase C: +pre, ReLU, dot with W2, reduce ----
    float srow[2][2];
    srow[0][0] = srow[0][1] = srow[1][0] = srow[1][1] = 0.f;
    #pragma unroll
    for (int mf = 0; mf < 2; mf++) {
        int r0 = rm + mf*16 + g;
        #pragma unroll
        for (int nf = 0; nf < 10; nf++) {
            int col = cn + nf*8 + 2*t4;
            float w0 = W2s[col], w1 = W2s[col + 1];
            __nv_bfloat162 pA = *(__nv_bfloat162*)(Hp + r0*160 + col);
            __nv_bfloat162 pB = *(__nv_bfloat162*)(Hp + (r0 + 8)*160 + col);
            float h0 = fmaxf(acc[mf][nf][0] + __bfloat162float(pA.x), 0.f);
            float h1 = fmaxf(acc[mf][nf][1] + __bfloat162float(pA.y), 0.f);
            float h2 = fmaxf(acc[mf][nf][2] + __bfloat162float(pB.x), 0.f);
            float h3 = fmaxf(acc[mf][nf][3] + __bfloat162float(pB.y), 0.f);
            srow[mf][0] += h0*w0 + h1*w1;
            srow[mf][1] += h2*w0 + h3*w1;
        }
    }
    #pragma unroll
    for (int mf = 0; mf < 2; mf++) {
        #pragma unroll
        for (int hh = 0; hh < 2; hh++) {
            float v = srow[mf][hh];
            v += __shfl_xor_sync(0xffffffffu, v, 1);
            v += __shfl_xor_sync(0xffffffffu, v, 2);
            srow[mf][hh] = v;
        }
    }
    if (t4 == 0) {
        #pragma unroll
        for (int mf = 0; mf < 2; mf++) {
            int r0 = rm + mf*16 + g;
            sred[r0*2 + wn]       = srow[mf][0];
            sred[(r0 + 8)*2 + wn] = srow[mf][1];
        }
    }
    __syncthreads();
    if (t < 128) scores[t] = sred[t*2] + sred[t*2 + 1] + b2[0] + msum[t];
    __syncthreads();

    // ---- Phase D: per-span softmax + pad ----
    if (warp < 2) {
        int sp = blockIdx.x * 2 + warp;
        int cnt = d_cnt[sp];
        float x0 = scores[warp*64 + lane];
        float x1 = scores[warp*64 + 32 + lane];
        bool v0 = lane < cnt;
        bool v1 = (lane + 32) < cnt;
        float m = 0.f;                       // epsilon logit = 0 always in the max
        if (v0) m = fmaxf(m, x0);
        if (v1) m = fmaxf(m, x1);
        #pragma unroll
        for (int o = 16; o; o >>= 1) m = fmaxf(m, __shfl_xor_sync(0xffffffffu, m, o));
        float e0 = v0 ? expf(x0 - m) : 0.f;
        float e1 = v1 ? expf(x1 - m) : 0.f;
        float sum = e0 + e1;
        #pragma unroll
        for (int o = 16; o; o >>= 1) sum += __shfl_xor_sync(0xffffffffu, sum, o);
        float eps = expf(-m);
        float inv = 1.f / (sum + eps);
        float* op = out + (size_t)sp * 65;
        op[lane]      = v0 ? e0 * inv : 1000.0f;
        op[lane + 32] = v1 ? e1 * inv : 1000.0f;
        if (lane == 0) op[64] = eps * inv;
    }
}

// ---------------- launcher ----------------
extern "C" void kernel_launch(void* const* d_in, const int* in_sizes, int n_in,
                              void* d_out, int out_size) {
    const float* g   = (const float*)d_in[0];
    const float* msc = (const float*)d_in[1];
    const float* de  = (const float*)d_in[2];
    const float* ge  = (const float*)d_in[3];
    const float* se  = (const float*)d_in[4];
    const float* W1  = (const float*)d_in[5];
    const float* b1  = (const float*)d_in[6];
    const float* W2  = (const float*)d_in[7];
    const float* b2  = (const float*)d_in[8];
    const void* mi = d_in[9];
    const void* ai = d_in[10];
    const void* di = d_in[11];
    const void* gn = d_in[12];
    const void* sp = d_in[13];
    const void* ac = d_in[14];
    float* out = (float*)d_out;

    cudaFuncSetAttribute(k_main, cudaFuncAttributeMaxDynamicSharedMemorySize, SMEM_MAIN);

    k_detect<<<1, 32>>>((const unsigned*)mi);
    k_index<<<(PP + 255)/256, 256>>>(mi, ai, di, gn, sp, ac);
    k_gb<<<(NN*GG + 255)/256, 256>>>(g);
    k_wct<<<(160*512 + 255)/256, 256>>>(W1);
    k_T<<<(192*160 + 255)/256, 256>>>(de, ge, se, W1, b1);
    k_uv<<<NN/8, 160>>>(g, W1);
    k_main<<<SS/2, 256, SMEM_MAIN>>>(msc, W2, b2, out);
}

// round 13
// speedup vs baseline: 1.6362x; 1.6362x over previous
#include <cuda_runtime.h>
#include <cuda_bf16.h>
#include <cstdint>

#define SS 4096
#define KK 64
#define NN 4096
#define GG 512
#define PP (SS*KK)

// ---------------- scratch (no allocation allowed) ----------------
__device__ int d_flag64;
__device__ __align__(16) int d_mi[PP];
__device__ __align__(16) int d_ai[PP];
__device__ __align__(16) int d_phi[PP];
__device__ __align__(16) int d_cnt[SS];
__device__ __align__(16) __nv_bfloat16 d_gb[NN*GG];      // g_i in bf16
__device__ __align__(16) __nv_bfloat16 d_wct[160*512];   // W1c^T in mma-FRAGMENT order (see k_wct)
__device__ __align__(16) __nv_bfloat16 d_Ub[NN*160];     // g @ W1a (bf16), pad cols zero
__device__ __align__(16) __nv_bfloat16 d_Vb[NN*160];     // g @ W1b (bf16)
__device__ __align__(16) __nv_bfloat16 d_Tb[192*160];    // phi-combo @ W1d + b1 (bf16)

// ---------------- helpers ----------------
__device__ __forceinline__ uint32_t smem_u32(const void* p) {
    uint32_t a;
    asm("{ .reg .u64 t; cvta.to.shared.u64 t, %1; cvt.u32.u64 %0, t; }" : "=r"(a) : "l"(p));
    return a;
}
__device__ __forceinline__ unsigned bmul2(unsigned x, unsigned y) {
    __nv_bfloat162 a = *reinterpret_cast<__nv_bfloat162*>(&x);
    __nv_bfloat162 b = *reinterpret_cast<__nv_bfloat162*>(&y);
    __nv_bfloat162 r = __hmul2(a, b);
    return *reinterpret_cast<unsigned*>(&r);
}
__device__ __forceinline__ float2 b2f(unsigned u) {
    __nv_bfloat162 h = *reinterpret_cast<__nv_bfloat162*>(&u);
    return __bfloat1622float2(h);
}

// ---------------- precompute kernels ----------------
__global__ void k_detect(const unsigned* __restrict__ m) {
    if (threadIdx.x == 0) {
        unsigned acc = 0;
        for (int t = 0; t < 64; t++) acc |= m[2*t + 1];
        d_flag64 = (acc == 0) ? 1 : 0;
    }
}

__global__ void k_index(const void* __restrict__ mi, const void* __restrict__ ai,
                        const void* __restrict__ di, const void* __restrict__ ge,
                        const void* __restrict__ sp, const void* __restrict__ ac) {
    int p = blockIdx.x * blockDim.x + threadIdx.x;
    int f = d_flag64;
    if (p < PP) {
        int a, b; long long d, gg, ss;
        if (f) {
            a = (int)((const long long*)mi)[p];
            b = (int)((const long long*)ai)[p];
            d  = ((const long long*)di)[p];
            gg = ((const long long*)ge)[p];
            ss = ((const long long*)sp)[p];
        } else {
            a = ((const int*)mi)[p];
            b = ((const int*)ai)[p];
            d  = ((const int*)di)[p];
            gg = ((const int*)ge)[p];
            ss = ((const int*)sp)[p];
        }
        int bk = (d>=1)+(d>=2)+(d>=3)+(d>=4)+(d>=8)+(d>=16)+(d>=32)+(d>=64);
        d_mi[p] = a;
        d_ai[p] = b;
        d_phi[p] = bk*21 + (int)gg*3 + (int)ss;
    }
    if (p < SS) {
        d_cnt[p] = f ? (int)((const long long*)ac)[p] : ((const int*)ac)[p];
    }
}

__global__ void k_gb(const float* __restrict__ g) {
    int i = blockIdx.x * 256 + threadIdx.x;
    if (i < NN*GG) d_gb[i] = __float2bfloat16(g[i]);
}

// W1c^T packed in mma fragment order:
// word index = (kc*20 + nf)*64 + lane*2 + half,  lane=(g,t4)
//   word = { W1c^T[n = nf*8+g, k = kc*16 + half*8 + 2*t4],  same n, k+1 }
// where W1c^T[n,k] = W1[1024+k][n]  (zero for n >= 150)
__global__ void k_wct(const float* __restrict__ W1) {
    int gid = blockIdx.x * 256 + threadIdx.x;   // word index, 0..40959
    if (gid < 40960) {
        int kc = gid / 1280;
        int r  = gid - kc*1280;
        int nf = r >> 6;
        int w  = r & 63;
        int l = w >> 1, half = w & 1;
        int g = l >> 2, t4 = l & 3;
        int n = nf*8 + g;
        int k = kc*16 + half*8 + 2*t4;
        float v0 = (n < 150) ? W1[(size_t)(1024 + k)*150 + n] : 0.f;
        float v1 = (n < 150) ? W1[(size_t)(1025 + k)*150 + n] : 0.f;
        __nv_bfloat162 pk = __floats2bfloat162_rn(v0, v1);
        ((unsigned*)d_wct)[gid] = *(unsigned*)&pk;
    }
}

__global__ void k_T(const float* __restrict__ de, const float* __restrict__ ge,
                    const float* __restrict__ se, const float* __restrict__ W1,
                    const float* __restrict__ b1) {
    int gid = blockIdx.x * blockDim.x + threadIdx.x;
    if (gid >= 192*160) return;
    int c = gid / 160, m = gid % 160;
    int d = c / 21, rr = c % 21, gg = rr / 3, sp = rr % 3;
    float val = 0.f;
    if (m < 150 && d < 9) {
        val = b1[m];
        #pragma unroll 4
        for (int q = 0; q < 20; q++) {
            val += de[d*20 + q]  * W1[(size_t)(1536 + q)*150 + m];
            val += ge[gg*20 + q] * W1[(size_t)(1556 + q)*150 + m];
            val += se[sp*20 + q] * W1[(size_t)(1576 + q)*150 + m];
        }
    }
    d_Tb[gid] = __float2bfloat16(val);
}

__global__ __launch_bounds__(160) void k_uv(const float* __restrict__ g,
                                            const float* __restrict__ W1) {
    __shared__ float gs[8*512];
    int n0 = blockIdx.x * 8;
    for (int idx = threadIdx.x; idx < 8*512; idx += 160)
        gs[idx] = g[(size_t)n0*512 + idx];
    __syncthreads();
    int m = threadIdx.x;
    if (m < 150) {
        float aU[8], aV[8];
        #pragma unroll
        for (int r = 0; r < 8; r++) { aU[r] = 0.f; aV[r] = 0.f; }
        for (int k = 0; k < 512; k++) {
            float wu = W1[(size_t)k*150 + m];
            float wv = W1[(size_t)(512 + k)*150 + m];
            #pragma unroll
            for (int r = 0; r < 8; r++) {
                float gv = gs[r*512 + k];
                aU[r] = fmaf(gv, wu, aU[r]);
                aV[r] = fmaf(gv, wv, aV[r]);
            }
        }
        #pragma unroll
        for (int r = 0; r < 8; r++) {
            d_Ub[(size_t)(n0 + r)*160 + m] = __float2bfloat16(aU[r]);
            d_Vb[(size_t)(n0 + r)*160 + m] = __float2bfloat16(aV[r]);
        }
    } else {
        #pragma unroll
        for (int r = 0; r < 8; r++) {
            d_Ub[(size_t)(n0 + r)*160 + m] = __float2bfloat16(0.f);
            d_Vb[(size_t)(n0 + r)*160 + m] = __float2bfloat16(0.f);
        }
    }
}

// ---------------- main fused kernel (mma.sync, zero-sync K loop) ----------------
// CTA = 128 pairs = 2 spans. 512 threads / 16 warps (8 M-tiles x 2 N-halves).
// smem:
//   Es [128 rows][stride 1040B] bf16, row-major, NO swizzle.
//     1040B = 65 x 16B (odd) -> 16B-chunk bank-group = (row + chunk) mod 8:
//     conflict-free for both the phase-A STS.128 and ldmatrix reads.
#define ES_STRIDE 1040
#define OFF_A    0
#define OFF_MSUM 133120
#define OFF_II   133632
#define OFF_JJ   134144
#define OFF_CC   134656
#define OFF_W2   135168
#define OFF_SC   135808
#define OFF_SR   136320
#define SMEM_MAIN 137344

__global__ __launch_bounds__(512, 1)
void k_main(const float* __restrict__ ms, const float* __restrict__ W2,
            const float* __restrict__ b2, float* __restrict__ out) {
    extern __shared__ char sm[];
    const int t = threadIdx.x;
    const int lane = t & 31, wid = t >> 5;
    const uint32_t sb = smem_u32(sm);
    const int pbase = blockIdx.x * 128;

    float* msum   = (float*)(sm + OFF_MSUM);
    int*   idxI   = (int*)(sm + OFF_II);
    int*   idxJ   = (int*)(sm + OFF_JJ);
    int*   idxC   = (int*)(sm + OFF_CC);
    float* W2s    = (float*)(sm + OFF_W2);
    float* scores = (float*)(sm + OFF_SC);
    float* sred   = (float*)(sm + OFF_SR);

    // ---- Phase A: gather + elementwise product into Es ----
    {
        const int pl = t & 127, qq = t >> 7;   // 4 threads per pair, 128B cols each
        const int p = pbase + pl;
        const int i = d_mi[p], j = d_ai[p];
        if (qq == 0) {
            msum[pl] = ms[i] + ms[j];
            idxI[pl] = i; idxJ[pl] = j; idxC[pl] = d_phi[p];
        }
        const uint4* gi4 = (const uint4*)(d_gb + (size_t)i*GG) + qq*16;
        const uint4* gj4 = (const uint4*)(d_gb + (size_t)j*GG) + qq*16;
        char* rowp = sm + OFF_A + pl*ES_STRIDE + qq*256;
        #pragma unroll
        for (int e = 0; e < 16; e++) {
            uint4 a = gi4[e], b = gj4[e], r;
            r.x = bmul2(a.x, b.x); r.y = bmul2(a.y, b.y);
            r.z = bmul2(a.z, b.z); r.w = bmul2(a.w, b.w);
            *(uint4*)(rowp + e*16) = r;
        }
        if (t < 160) W2s[t] = (t < 150) ? __ldg(W2 + t) : 0.f;
    }
    __syncthreads();   // the ONLY barrier before the epilogue

    // ---- K loop: 32 chunks of k16, B fragments streamed from L2 ----
    const int mw = wid >> 1, nw = wid & 1;
    const int g = lane >> 2, t4 = lane & 3;

    // ldmatrix.x4 lane address: matrices {m0-7,k0-7},{m8-15,k0-7},{m0-7,k8-15},{m8-15,k8-15}
    const uint32_t arow = sb + OFF_A
        + (uint32_t)(mw*16 + (lane & 7) + (lane & 8)) * ES_STRIDE
        + (uint32_t)((lane >> 4) & 1) * 16;

    const uint2* wsrc = (const uint2*)d_wct + (size_t)(nw*10)*32 + lane;

    float acc[10][4];
    #pragma unroll
    for (int q = 0; q < 10; q++)
        #pragma unroll
        for (int e = 0; e < 4; e++) acc[q][e] = 0.f;

    uint2 bA[10], bB[10];
    #pragma unroll
    for (int q = 0; q < 10; q++) bA[q] = wsrc[q*32];

    for (int kc = 0; kc < 32; kc++) {
        // prefetch next chunk's B fragments into the spare buffer
        if (kc < 31) {
            #pragma unroll
            for (int q = 0; q < 10; q++) bB[q] = wsrc[((kc + 1)*20 + q)*32];
        }
        uint32_t a0, a1, a2, a3;
        asm volatile("ldmatrix.sync.aligned.m8n8.x4.shared.b16 {%0,%1,%2,%3}, [%4];"
                     : "=r"(a0), "=r"(a1), "=r"(a2), "=r"(a3)
                     : "r"(arow + (uint32_t)kc*32));
        #pragma unroll
        for (int q = 0; q < 10; q++) {
            asm volatile(
                "mma.sync.aligned.m16n8k16.row.col.f32.bf16.bf16.f32 "
                "{%0,%1,%2,%3}, {%4,%5,%6,%7}, {%8,%9}, {%0,%1,%2,%3};"
                : "+f"(acc[q][0]), "+f"(acc[q][1]), "+f"(acc[q][2]), "+f"(acc[q][3])
                : "r"(a0), "r"(a1), "r"(a2), "r"(a3), "r"(bA[q].x), "r"(bA[q].y));
        }
        #pragma unroll
        for (int q = 0; q < 10; q++) bA[q] = bB[q];
    }

    // ---- Epilogue: + U/V/T gather (bf16 from L2), ReLU, dot W2 ----
    {
        const int r0 = mw*16 + g, r1 = r0 + 8;
        const int i0 = idxI[r0], j0 = idxJ[r0], c0 = idxC[r0];
        const int i1 = idxI[r1], j1 = idxJ[r1], c1 = idxC[r1];
        float s0 = 0.f, s1 = 0.f;
        #pragma unroll
        for (int q = 0; q < 10; q++) {
            const int c = nw*80 + q*8 + 2*t4;
            float2 u0 = b2f(*(const unsigned*)(d_Ub + (size_t)i0*160 + c));
            float2 v0 = b2f(*(const unsigned*)(d_Vb + (size_t)j0*160 + c));
            float2 t0 = b2f(*(const unsigned*)(d_Tb + (size_t)c0*160 + c));
            float2 u1 = b2f(*(const unsigned*)(d_Ub + (size_t)i1*160 + c));
            float2 v1 = b2f(*(const unsigned*)(d_Vb + (size_t)j1*160 + c));
            float2 t1 = b2f(*(const unsigned*)(d_Tb + (size_t)c1*160 + c));
            float w0 = W2s[c], w1 = W2s[c + 1];
            float h00 = fmaxf(acc[q][0] + u0.x + v0.x + t0.x, 0.f);
            float h01 = fmaxf(acc[q][1] + u0.y + v0.y + t0.y, 0.f);
            float h10 = fmaxf(acc[q][2] + u1.x + v1.x + t1.x, 0.f);
            float h11 = fmaxf(acc[q][3] + u1.y + v1.y + t1.y, 0.f);
            s0 += h00*w0 + h01*w1;
            s1 += h10*w0 + h11*w1;
        }
        s0 += __shfl_xor_sync(0xffffffffu, s0, 1);
        s0 += __shfl_xor_sync(0xffffffffu, s0, 2);
        s1 += __shfl_xor_sync(0xffffffffu, s1, 1);
        s1 += __shfl_xor_sync(0xffffffffu, s1, 2);
        if (t4 == 0) {
            sred[r0*2 + nw] = s0;
            sred[r1*2 + nw] = s1;
        }
    }
    __syncthreads();
    if (t < 128) scores[t] = sred[t*2] + sred[t*2 + 1] + b2[0] + msum[t];
    __syncthreads();

    // ---- Softmax + pad ----
    if (wid < 2) {
        int sp = blockIdx.x*2 + wid;
        int cnt = d_cnt[sp];
        float x0 = scores[wid*64 + lane];
        float x1 = scores[wid*64 + 32 + lane];
        bool v0 = lane < cnt;
        bool v1 = (lane + 32) < cnt;
        float m = 0.f;                      // epsilon logit 0 is always in the max
        if (v0) m = fmaxf(m, x0);
        if (v1) m = fmaxf(m, x1);
        #pragma unroll
        for (int o = 16; o; o >>= 1) m = fmaxf(m, __shfl_xor_sync(0xffffffffu, m, o));
        float e0 = v0 ? expf(x0 - m) : 0.f;
        float e1 = v1 ? expf(x1 - m) : 0.f;
        float sum = e0 + e1;
        #pragma unroll
        for (int o = 16; o; o >>= 1) sum += __shfl_xor_sync(0xffffffffu, sum, o);
        float eps = expf(-m);
        float inv = 1.f / (sum + eps);
        float* op = out + (size_t)sp * 65;
        op[lane]      = v0 ? e0 * inv : 1000.0f;
        op[lane + 32] = v1 ? e1 * inv : 1000.0f;
        if (lane == 0) op[64] = eps * inv;
    }
}

// ---------------- launcher ----------------
extern "C" void kernel_launch(void* const* d_in, const int* in_sizes, int n_in,
                              void* d_out, int out_size) {
    const float* g   = (const float*)d_in[0];
    const float* msc = (const float*)d_in[1];
    const float* de  = (const float*)d_in[2];
    const float* ge  = (const float*)d_in[3];
    const float* se  = (const float*)d_in[4];
    const float* W1  = (const float*)d_in[5];
    const float* b1  = (const float*)d_in[6];
    const float* W2  = (const float*)d_in[7];
    const float* b2  = (const float*)d_in[8];
    const void* mi = d_in[9];
    const void* ai = d_in[10];
    const void* di = d_in[11];
    const void* gn = d_in[12];
    const void* sp = d_in[13];
    const void* ac = d_in[14];
    float* out = (float*)d_out;

    cudaFuncSetAttribute(k_main, cudaFuncAttributeMaxDynamicSharedMemorySize, SMEM_MAIN);

    k_detect<<<1, 32>>>((const unsigned*)mi);
    k_index<<<(PP + 255)/256, 256>>>(mi, ai, di, gn, sp, ac);
    k_gb<<<(NN*GG + 255)/256, 256>>>(g);
    k_wct<<<160, 256>>>(W1);
    k_T<<<(192*160 + 255)/256, 256>>>(de, ge, se, W1, b1);
    k_uv<<<NN/8, 160>>>(g, W1);
    k_main<<<SS/2, 512, SMEM_MAIN>>>(msc, W2, b2, out);
}